// round 3
// baseline (speedup 1.0000x reference)
#include <cuda_runtime.h>
#include <cuda_bf16.h>
#include <cstdint>

// Problem constants (fixed by the dataset): B=1024, T=512, K=64 tags.
#define KTAG 64
#define MAXB 1024
#define MAXT 512
#define NEGV -10000.0f

// Interleaved scratch: g_fm[b][t][j] = (fv, m) pair.
//   fv = viterbi value AFTER step t (max + emission)
//   m  = max_prev(fv_prev + w[j][prev]) BEFORE emission (backtrace target)
__device__ float g_fm[(size_t)MAXB * MAXT * KTAG * 2];
__device__ int   g_last[MAXB];
__device__ float g_scratch[(size_t)MAXB * MAXT];
__device__ float g_scratch_score[MAXB];

// ---- packed f32x2 add (FADD2: 2 floats per fma-pipe slot) ----
#define ADD2(d, a, b) asm("add.rn.f32x2 %0, %1, %2;" : "=l"(d) : "l"(a), "l"(b))

__device__ __forceinline__ void unpack2(unsigned long long v, float& lo, float& hi) {
    unsigned int l, h;
    asm("mov.b64 {%0, %1}, %2;" : "=r"(l), "=r"(h) : "l"(v));
    lo = __uint_as_float(l);
    hi = __uint_as_float(h);
}

// ---- cp.async helpers ----
__device__ __forceinline__ void cp_async16(void* smem_dst, const void* gmem_src) {
    unsigned int d = (unsigned int)__cvta_generic_to_shared(smem_dst);
    asm volatile("cp.async.cg.shared.global [%0], [%1], 16;" :: "r"(d), "l"(gmem_src));
}
#define CP_COMMIT()  asm volatile("cp.async.commit_group;")
#define CP_WAIT(n)   asm volatile("cp.async.wait_group %0;" :: "n"(n))

// ============================================================================
// Forward: one block per batch, 64 threads (thread j owns "next" tag j).
// new_fv[j] = max_prev(fv[prev] + w[j][prev]) + feat[t][j]
// Adds via FADD2 (fma pipe, halved slots); maxes scalar FMNMX (alu pipe).
// ============================================================================
__global__ __launch_bounds__(KTAG) void crf_forward(
    const float* __restrict__ feats,
    const float* __restrict__ weights,
    const int* __restrict__ lens,
    float* __restrict__ score_out,
    int T)
{
    const int b = blockIdx.x;
    const int j = threadIdx.x;          // next tag
    const int lane = j & 31;
    const int warp = j >> 5;

    __shared__ __align__(16) float fv_sh[2][KTAG];   // ping-pong: 1 bar/step
    __shared__ float red_v[2];
    __shared__ int   red_i[2];

    // Weight row w[j][0..63] in registers as 32 packed f32x2.
    unsigned long long wp[KTAG / 2];
    {
        const ulonglong2* wrow = reinterpret_cast<const ulonglong2*>(weights + j * KTAG);
        #pragma unroll
        for (int i = 0; i < KTAG / 4; ++i) {
            ulonglong2 v = wrow[i];
            wp[2 * i]     = v.x;
            wp[2 * i + 1] = v.y;
        }
    }

    fv_sh[0][j] = (j == 0) ? 0.0f : NEGV;

    const int len = lens[b];            // 1..T
    const size_t base = (size_t)b * T * KTAG;
    float2* __restrict__ fm_out = reinterpret_cast<float2*>(g_fm) + base;

    // 4-deep emission prefetch ring (bounded by len).
    float fring[4];
    #pragma unroll
    for (int k = 0; k < 4; ++k)
        fring[k] = (k < len) ? feats[base + (size_t)k * KTAG + j] : 0.0f;

    __syncthreads();

    for (int t = 0; t < len; ++t) {
        const int rb = t & 1;

        float feat = fring[t & 3];
        if (t + 4 < len)
            fring[t & 3] = feats[base + (size_t)(t + 4) * KTAG + j];

        float a0 = -3.0e38f, a1 = -3.0e38f, a2 = -3.0e38f, a3 = -3.0e38f;
        float a4 = -3.0e38f, a5 = -3.0e38f, a6 = -3.0e38f, a7 = -3.0e38f;
        const ulonglong2* fvv = reinterpret_cast<const ulonglong2*>(fv_sh[rb]);
        #pragma unroll
        for (int i = 0; i < 16; i += 2) {
            ulonglong2 fa = fvv[i];
            ulonglong2 fb = fvv[i + 1];
            unsigned long long s0, s1, s2, s3;
            ADD2(s0, fa.x, wp[2 * i + 0]);
            ADD2(s1, fa.y, wp[2 * i + 1]);
            ADD2(s2, fb.x, wp[2 * i + 2]);
            ADD2(s3, fb.y, wp[2 * i + 3]);
            float x0, x1, x2, x3, x4, x5, x6, x7;
            unpack2(s0, x0, x1); unpack2(s1, x2, x3);
            unpack2(s2, x4, x5); unpack2(s3, x6, x7);
            a0 = fmaxf(a0, x0); a1 = fmaxf(a1, x1);
            a2 = fmaxf(a2, x2); a3 = fmaxf(a3, x3);
            a4 = fmaxf(a4, x4); a5 = fmaxf(a5, x5);
            a6 = fmaxf(a6, x6); a7 = fmaxf(a7, x7);
        }
        a0 = fmaxf(a0, a1); a2 = fmaxf(a2, a3);
        a4 = fmaxf(a4, a5); a6 = fmaxf(a6, a7);
        a0 = fmaxf(a0, a2); a4 = fmaxf(a4, a6);
        float maxv = fmaxf(a0, a4);
        float nf = maxv + feat;

        fv_sh[rb ^ 1][j] = nf;
        fm_out[(size_t)t * KTAG + j] = make_float2(nf, maxv);   // STG.64
        __syncthreads();
    }

    // Terminal: fv + weights[END=1][prev]; argmax, first-index tie-break.
    float v = fv_sh[len & 1][j] + weights[1 * KTAG + j];
    int idx = j;
    #pragma unroll
    for (int off = 16; off; off >>= 1) {
        float ov = __shfl_xor_sync(0xffffffffu, v, off);
        int   oi = __shfl_xor_sync(0xffffffffu, idx, off);
        if (ov > v || (ov == v && oi < idx)) { v = ov; idx = oi; }
    }
    if (lane == 0) { red_v[warp] = v; red_i[warp] = idx; }
    __syncthreads();
    if (j == 0) {
        float v0 = red_v[0], v1 = red_v[1];
        if (v1 > v0) { score_out[b] = v1; g_last[b] = red_i[1]; }
        else         { score_out[b] = v0; g_last[b] = red_i[0]; }
    }
}

// ============================================================================
// Backward: one warp per batch. Argmax recovered by equality match:
//   tag' = first p with fv_after[t-1][p] + w[tag][p] == m[t][tag]
// (bit-exact: same FADD operands as forward). Chunked staging of the
// interleaved (fv, m) rows through shared with cp.async double-buffering.
// ============================================================================
#define CH 8    // timesteps per staged chunk; buffer holds CH+1 rows

__global__ __launch_bounds__(32) void crf_backward(
    const float* __restrict__ weights,
    const int* __restrict__ lens,
    float* __restrict__ path_out,
    int T)
{
    const int b = blockIdx.x;
    const int lane = threadIdx.x;

    __shared__ __align__(16) float w_sh[KTAG * KTAG];        // 16 KB
    __shared__ __align__(16) float buf[2][(CH + 1) * 128];   // 9.2 KB (fv,m rows)
    __shared__ float path_sh[MAXT];                          // 2 KB

    for (int q = lane; q < (KTAG * KTAG) / 4; q += 32)
        reinterpret_cast<float4*>(w_sh)[q] = reinterpret_cast<const float4*>(weights)[q];

    const int len = lens[b];
    int tag = g_last[b];
    const size_t base = (size_t)b * T * KTAG;            // in float2 units
    const float* __restrict__ fm = g_fm + (base << 1);   // floats

    // Stage rows r = lo-1 .. lo-1+CH (interleaved fv,m; 128 floats = 32x16B each).
    auto stage = [&](int lo, int bi) {
        const int r0 = lo - 1;
        #pragma unroll
        for (int s = 0; s < CH + 1; ++s) {
            const int r = r0 + s;
            if (r >= 0 && r < len)
                cp_async16(&buf[bi][s * 128 + lane * 4],
                           fm + ((size_t)r * 128 + lane * 4));
        }
        CP_COMMIT();
    };

    int bi = 0;
    stage(T - CH, 0);

    for (int hi = T; hi > 0; hi -= CH) {
        const int lo = hi - CH;
        if (lo > 0) { stage(lo - CH, bi ^ 1); CP_WAIT(1); }
        else        { CP_WAIT(0); }
        __syncwarp();

        const float* bufc = buf[bi];
        for (int t = hi - 1; t >= lo; --t) {
            if (lane == 0) path_sh[t] = (float)tag;
            if (t >= 1 && t < len) {
                const float target = bufc[(t - lo + 1) * 128 + 2 * tag + 1]; // m[t][tag]
                const float* rowb = bufc + (t - lo) * 128;                   // fv[t-1]
                const float* wr = w_sh + tag * KTAG;
                float2 f0 = *reinterpret_cast<const float2*>(rowb + 2 * lane);
                float2 f1 = *reinterpret_cast<const float2*>(rowb + 64 + 2 * lane);
                const bool p0 = (f0.x + wr[lane])      == target;
                const bool p1 = (f1.x + wr[lane + 32]) == target;
                const unsigned b0 = __ballot_sync(0xffffffffu, p0);
                const unsigned b1 = __ballot_sync(0xffffffffu, p1);
                tag = b0 ? (__ffs(b0) - 1) : (__ffs(b1) + 31);
            }
        }
        bi ^= 1;
        __syncwarp();   // all lanes done reading before this buffer is re-staged
    }

    for (int q = lane; q < T; q += 32)
        path_out[(size_t)b * T + q] = path_sh[q];
}

extern "C" void kernel_launch(void* const* d_in, const int* in_sizes, int n_in,
                              void* d_out, int out_size) {
    const float* feats   = (const float*)d_in[0];
    const float* weights = (const float*)d_in[1];
    const int*   lens    = (const int*)d_in[2];

    const int B = in_sizes[2];
    const int K = KTAG;
    const int T = in_sizes[0] / (B * K);

    float* out = (float*)d_out;
    float* score_ptr;
    float* path_ptr;

    if (out_size == B * (T + 1)) {          // [score B | paths B*T]
        score_ptr = out;
        path_ptr  = out + B;
    } else if (out_size == B) {             // score only
        score_ptr = out;
        void* p; cudaGetSymbolAddress(&p, g_scratch);
        path_ptr = (float*)p;
    } else {                                // paths only
        path_ptr = out;
        void* p; cudaGetSymbolAddress(&p, g_scratch_score);
        score_ptr = (float*)p;
    }

    crf_forward<<<B, KTAG>>>(feats, weights, lens, score_ptr, T);
    crf_backward<<<B, 32>>>(weights, lens, path_ptr, T);
}